// round 6
// baseline (speedup 1.0000x reference)
#include <cuda_runtime.h>
#include <cuda_bf16.h>
#include <math.h>
#include <stdint.h>

#define D_MODEL   1024
#define D_STATE   16
#define D_CONV    4
#define D_INNER   2048
#define DT_RANK   64
#define IN_SIZE   512
#define OUT_SIZE  512
#define BATCH     2048
#define XDB_COLS  96
#define STATE_W   20

typedef __nv_bfloat16 bf16;

// ---------------- fp32 scratch ----------------
__device__ float g_xz[BATCH * 2 * D_INNER];
__device__ float g_xc[BATCH * D_INNER];
__device__ float g_xdb[BATCH * XDB_COLS];
__device__ float g_dt[BATCH * D_INNER];
// ---------------- bf16 split scratch ----------------
__device__ bf16 g_h_hi[BATCH * D_MODEL],   g_h_lo[BATCH * D_MODEL];
__device__ bf16 g_x_hi[BATCH * IN_SIZE],   g_x_lo[BATCH * IN_SIZE];
__device__ bf16 g_xc_hi[BATCH * D_INNER],  g_xc_lo[BATCH * D_INNER];
__device__ bf16 g_y_hi[BATCH * D_INNER],   g_y_lo[BATCH * D_INNER];
__device__ bf16 g_co_hi[BATCH * D_MODEL],  g_co_lo[BATCH * D_MODEL];
__device__ bf16 g_xdb_hi[BATCH * XDB_COLS], g_xdb_lo[BATCH * XDB_COLS];
__device__ bf16 g_w1_hi[D_MODEL * IN_SIZE],     g_w1_lo[D_MODEL * IN_SIZE];
__device__ bf16 g_w2_hi[2 * D_INNER * D_MODEL], g_w2_lo[2 * D_INNER * D_MODEL];
__device__ bf16 g_w4_hi[XDB_COLS * D_INNER],    g_w4_lo[XDB_COLS * D_INNER];
__device__ bf16 g_w5_hi[D_INNER * DT_RANK],     g_w5_lo[D_INNER * DT_RANK];
__device__ bf16 g_w7_hi[D_MODEL * D_INNER],     g_w7_lo[D_MODEL * D_INNER];
__device__ bf16 g_w8_hi[OUT_SIZE * D_MODEL],    g_w8_lo[OUT_SIZE * D_MODEL];

// ---------------- helpers ----------------
__device__ __forceinline__ float softplusf(float x) {
    return (x > 0.f) ? (x + log1pf(__expf(-x))) : log1pf(__expf(x));
}
__device__ __forceinline__ float siluf(float x) {
    return x / (1.f + __expf(-x));
}
__device__ __forceinline__ void bsplit(float v, bf16& h, bf16& l) {
    h = __float2bfloat16_rn(v);
    l = __float2bfloat16_rn(v - __bfloat162float(h));
}
__device__ __forceinline__ void mmabf(float* c, const uint32_t* a, const uint32_t* b) {
    asm volatile(
        "mma.sync.aligned.m16n8k16.row.col.f32.bf16.bf16.f32 "
        "{%0,%1,%2,%3}, {%4,%5,%6,%7}, {%8,%9}, {%0,%1,%2,%3};"
        : "+f"(c[0]), "+f"(c[1]), "+f"(c[2]), "+f"(c[3])
        : "r"(a[0]), "r"(a[1]), "r"(a[2]), "r"(a[3]), "r"(b[0]), "r"(b[1]));
}
__device__ __forceinline__ void cpa16(uint32_t dst, const void* src, bool p) {
    int sz = p ? 16 : 0;
    asm volatile("cp.async.cg.shared.global [%0], [%1], 16, %2;\n"
                 :: "r"(dst), "l"(src), "r"(sz));
}
__device__ __forceinline__ void ldm4(uint32_t* r, uint32_t addr) {
    asm volatile("ldmatrix.sync.aligned.m8n8.x4.shared.b16 {%0,%1,%2,%3}, [%4];"
                 : "=r"(r[0]), "=r"(r[1]), "=r"(r[2]), "=r"(r[3]) : "r"(addr));
}

// ======================================================================
// 2xBF16-split tensor GEMM. C[M,N] = A[M,K] @ B[N,K]^T (bf16 hi/lo pairs,
// K contiguous). BM=BN=128, BK=64 elem, 256 thr, warps 4(m)x2(n),
// warp tile 32x64. 3-stage cp.async pipeline, ldmatrix fragment loads.
// ======================================================================
#define STAGE_U32  (4 * 128 * 36)            // Ah,Al,Bh,Bl tiles (uint32 units)
#define STAGE_B    (STAGE_U32 * 4)           // 73728 bytes
#define TG_SMEM    (3 * STAGE_B)             // 221184 bytes

template<int EPI, bool SPLITK, bool WSPLIT>
__global__ void __launch_bounds__(256, 1)
bgemm(const bf16* __restrict__ Ahi, const bf16* __restrict__ Alo,
      const bf16* __restrict__ Bhi, const bf16* __restrict__ Blo,
      float* __restrict__ C, bf16* __restrict__ Chi, bf16* __restrict__ Clo,
      const float* __restrict__ bias,
      int M, int N, int K, int lda, int ldb, int ldc)
{
    extern __shared__ uint32_t smbuf[];
    constexpr int TSZ = 128 * 36;     // one tile in uint32 units

    const uint32_t* A32h = reinterpret_cast<const uint32_t*>(Ahi);
    const uint32_t* A32l = reinterpret_cast<const uint32_t*>(Alo);
    const uint32_t* B32h = reinterpret_cast<const uint32_t*>(Bhi);
    const uint32_t* B32l = reinterpret_cast<const uint32_t*>(Blo);
    const int ldap = lda >> 1, ldbp = ldb >> 1;

    const int tid  = threadIdx.x;
    const int lane = tid & 31;
    const int warp = tid >> 5;
    const int wm   = warp & 3;
    const int wn   = warp >> 2;
    const int m0   = blockIdx.y * 128;
    const int n0   = blockIdx.x * 128;
    const int Kc   = SPLITK ? (K / gridDim.z) : K;
    const int k0b  = SPLITK ? (blockIdx.z * Kc) : 0;
    const int T    = Kc / 64;

    const int lr = tid >> 3;              // 0..31 fill row
    const int lc = (tid & 7) * 4;         // fill pair col

    // ldmatrix lane geometry
    const uint32_t sbase = (uint32_t)__cvta_generic_to_shared(smbuf);
    const int qrow = ((lane & 8) ? 8 : 0) + (lane & 7);
    const int kSel = (lane & 16) ? 16 : 0;           // +16B for k8..15
    const int aRow = wm * 32 + qrow;
    const int bRow = wn * 64 + qrow;

    float acc[2][8][4];
#pragma unroll
    for (int i = 0; i < 2; i++)
#pragma unroll
        for (int j = 0; j < 8; j++)
#pragma unroll
            for (int q = 0; q < 4; q++) acc[i][j][q] = 0.f;

    auto fill = [&](int t, int st) {
        uint32_t* Ah = smbuf + st * STAGE_U32;
        uint32_t* Al = Ah + TSZ;
        uint32_t* Bh = Al + TSZ;
        uint32_t* Bl = Bh + TSZ;
        const int kp0 = (k0b + t * 64) >> 1;
#pragma unroll
        for (int it = 0; it < 4; it++) {
            const int row = lr + it * 32;
            const size_t g = (size_t)(m0 + row) * ldap + kp0 + lc;
            cpa16((uint32_t)__cvta_generic_to_shared(&Ah[row * 36 + lc]), A32h + g, true);
            cpa16((uint32_t)__cvta_generic_to_shared(&Al[row * 36 + lc]), A32l + g, true);
        }
#pragma unroll
        for (int it = 0; it < 4; it++) {
            const int row = lr + it * 32;
            const bool p = SPLITK ? ((n0 + row) < N) : true;
            const size_t g = (size_t)(n0 + row) * ldbp + kp0 + lc;
            cpa16((uint32_t)__cvta_generic_to_shared(&Bh[row * 36 + lc]), B32h + g, p);
            cpa16((uint32_t)__cvta_generic_to_shared(&Bl[row * 36 + lc]), B32l + g, p);
        }
    };

    auto compute = [&](int st) {
        const uint32_t stb = sbase + st * STAGE_B;
        const uint32_t AhB = stb;
        const uint32_t AlB = stb + TSZ * 4;
        const uint32_t BhB = stb + 2 * TSZ * 4;
        const uint32_t BlB = stb + 3 * TSZ * 4;
#pragma unroll
        for (int sl = 0; sl < 4; sl++) {       // 4 slices of k16 per chunk
            const int colb = sl * 32 + kSel;
            uint32_t ah[2][4], al[2][4];
#pragma unroll
            for (int mt = 0; mt < 2; mt++) {
                const uint32_t off = (uint32_t)(aRow + mt * 16) * 144 + colb;
                ldm4(ah[mt], AhB + off);
                ldm4(al[mt], AlB + off);
            }
            uint32_t bh[8][2], bl[8][2];
#pragma unroll
            for (int np = 0; np < 4; np++) {
                const uint32_t off = (uint32_t)(bRow + np * 16) * 144 + colb;
                uint32_t t4[4];
                ldm4(t4, BhB + off);
                bh[2*np][0] = t4[0]; bh[2*np][1] = t4[2];
                bh[2*np+1][0] = t4[1]; bh[2*np+1][1] = t4[3];
                ldm4(t4, BlB + off);
                bl[2*np][0] = t4[0]; bl[2*np][1] = t4[2];
                bl[2*np+1][0] = t4[1]; bl[2*np+1][1] = t4[3];
            }
#pragma unroll
            for (int mt = 0; mt < 2; mt++)
#pragma unroll
                for (int nt = 0; nt < 8; nt++) {
                    mmabf(acc[mt][nt], ah[mt], bl[nt]);   // hi * lo'
                    mmabf(acc[mt][nt], al[mt], bh[nt]);   // lo * hi'
                    mmabf(acc[mt][nt], ah[mt], bh[nt]);   // hi * hi'
                }
        }
    };

    fill(0, 0);
    asm volatile("cp.async.commit_group;" ::: "memory");
    if (T > 1) {
        fill(1, 1);
        asm volatile("cp.async.commit_group;" ::: "memory");
    }
    int st = 0, stn = 2;                      // stage of t, stage for t+2
    for (int t = 0; t < T; t++) {
        if (t + 1 < T) asm volatile("cp.async.wait_group 1;" ::: "memory");
        else           asm volatile("cp.async.wait_group 0;" ::: "memory");
        __syncthreads();
        if (t + 2 < T) {
            fill(t + 2, stn);
            asm volatile("cp.async.commit_group;" ::: "memory");
        }
        compute(st);
        st = (st == 2) ? 0 : st + 1;
        stn = (stn == 2) ? 0 : stn + 1;
    }

    // ---- epilogue
#pragma unroll
    for (int mt = 0; mt < 2; mt++) {
        const int mr = m0 + wm * 32 + mt * 16 + (lane >> 2);
#pragma unroll
        for (int nt = 0; nt < 8; nt++) {
            const int nc = n0 + wn * 64 + nt * 8 + (lane & 3) * 2;
            float v0 = acc[mt][nt][0], v1 = acc[mt][nt][1];
            float v2 = acc[mt][nt][2], v3 = acc[mt][nt][3];
            if (SPLITK) {
                if (nc < N) {
                    atomicAdd(&C[(size_t)mr * ldc + nc], v0);
                    atomicAdd(&C[(size_t)mr * ldc + nc + 1], v1);
                    atomicAdd(&C[(size_t)(mr + 8) * ldc + nc], v2);
                    atomicAdd(&C[(size_t)(mr + 8) * ldc + nc + 1], v3);
                }
                continue;
            }
            if (EPI >= 1) {
                const float b0 = bias[nc], b1 = bias[nc + 1];
                v0 += b0; v1 += b1; v2 += b0; v3 += b1;
            }
            if (EPI == 2) {
                v0 = softplusf(v0); v1 = softplusf(v1);
                v2 = softplusf(v2); v3 = softplusf(v3);
            }
            if (WSPLIT) {
                bf16 h0, l0, h1, l1, h2, l2, h3, l3;
                bsplit(v0, h0, l0); bsplit(v1, h1, l1);
                bsplit(v2, h2, l2); bsplit(v3, h3, l3);
                __nv_bfloat162 ha = {h0, h1}, hb = {h2, h3};
                __nv_bfloat162 la = {l0, l1}, lb = {l2, l3};
                *reinterpret_cast<uint32_t*>(&Chi[(size_t)mr * ldc + nc])       = *(uint32_t*)&ha;
                *reinterpret_cast<uint32_t*>(&Chi[(size_t)(mr + 8) * ldc + nc]) = *(uint32_t*)&hb;
                *reinterpret_cast<uint32_t*>(&Clo[(size_t)mr * ldc + nc])       = *(uint32_t*)&la;
                *reinterpret_cast<uint32_t*>(&Clo[(size_t)(mr + 8) * ldc + nc]) = *(uint32_t*)&lb;
            } else {
                *reinterpret_cast<float2*>(&C[(size_t)mr * ldc + nc])       = make_float2(v0, v1);
                *reinterpret_cast<float2*>(&C[(size_t)(mr + 8) * ldc + nc]) = make_float2(v2, v3);
            }
        }
    }
}

// ---------------- split pass ----------------
__global__ void __launch_bounds__(256)
split_kernel(const float* __restrict__ in, bf16* __restrict__ hi,
             bf16* __restrict__ lo, int n4)
{
    int i = blockIdx.x * 256 + threadIdx.x;
    if (i < n4) {
        float4 v = reinterpret_cast<const float4*>(in)[i];
        bf16 h0, l0, h1, l1, h2, l2, h3, l3;
        bsplit(v.x, h0, l0); bsplit(v.y, h1, l1);
        bsplit(v.z, h2, l2); bsplit(v.w, h3, l3);
        __nv_bfloat162 hA = {h0, h1}, hB = {h2, h3};
        __nv_bfloat162 lA = {l0, l1}, lB = {l2, l3};
        uint2 hu = {*(uint32_t*)&hA, *(uint32_t*)&hB};
        uint2 lu = {*(uint32_t*)&lA, *(uint32_t*)&lB};
        reinterpret_cast<uint2*>(hi)[i] = hu;
        reinterpret_cast<uint2*>(lo)[i] = lu;
    }
}

// ---------------- transpose + split: KxN fp32 -> NxK bf16 hi/lo ----------------
__global__ void __launch_bounds__(256)
tsplit_kernel(const float* __restrict__ in, bf16* __restrict__ hi,
              bf16* __restrict__ lo, int K, int N)
{
    __shared__ float t[32][33];
    const int k0 = blockIdx.y * 32, n0 = blockIdx.x * 32;
    const int tx = threadIdx.x & 31, ty = threadIdx.x >> 5;
#pragma unroll
    for (int j = ty; j < 32; j += 8)
        t[j][tx] = in[(size_t)(k0 + j) * N + n0 + tx];
    __syncthreads();
#pragma unroll
    for (int j = ty; j < 32; j += 8) {
        float v = t[tx][j];
        bf16 h, l; bsplit(v, h, l);
        hi[(size_t)(n0 + j) * K + k0 + tx] = h;
        lo[(size_t)(n0 + j) * K + k0 + tx] = l;
    }
}

__global__ void zero_kernel(float* __restrict__ p, int n) {
    int i = blockIdx.x * blockDim.x + threadIdx.x;
    if (i < n) p[i] = 0.f;
}

// ---------------- conv-shift + silu ----------------
__global__ void __launch_bounds__(256)
conv_kernel(const float* __restrict__ rnn, const float* __restrict__ xz,
            const float* __restrict__ conv_w, const float* __restrict__ conv_b,
            float* __restrict__ out_states, float* __restrict__ xc,
            bf16* __restrict__ xch, bf16* __restrict__ xcl)
{
    const size_t idx = (size_t)blockIdx.x * 256 + threadIdx.x;
    const int b = (int)(idx / D_INNER);
    const int d = (int)(idx % D_INNER);
    const size_t srow = (size_t)b * (D_INNER * STATE_W) + (size_t)d * STATE_W;

    float4 cs = *reinterpret_cast<const float4*>(rnn + srow);
    float xi = xz[(size_t)b * (2 * D_INNER) + d];
    float4 w = *reinterpret_cast<const float4*>(conv_w + d * 4);

    float v = cs.y * w.x + cs.z * w.y + cs.w * w.z + xi * w.w + conv_b[d];
    float s = siluf(v);
    xc[idx] = s;
    bf16 h, l; bsplit(s, h, l);
    xch[idx] = h; xcl[idx] = l;
    *reinterpret_cast<float4*>(out_states + srow) = make_float4(cs.y, cs.z, cs.w, xi);
}

// ---------------- SSM state update + gating ----------------
__global__ void __launch_bounds__(256)
ssm_kernel(const float* __restrict__ rnn, const float* __restrict__ xz,
           const float* __restrict__ xdb, const float* __restrict__ dt_,
           const float* __restrict__ xc_, const float* __restrict__ A_log,
           const float* __restrict__ Dp,
           float* __restrict__ out_states, bf16* __restrict__ yh, bf16* __restrict__ yl)
{
    const int b = blockIdx.y;
    const int d = blockIdx.x * 256 + threadIdx.x;

    __shared__ float sBC[32];
    if (threadIdx.x < 32) sBC[threadIdx.x] = xdb[(size_t)b * XDB_COLS + DT_RANK + threadIdx.x];
    __syncthreads();

    const size_t bd = (size_t)b * D_INNER + d;
    const float dt = dt_[bd];
    const float xc = xc_[bd];
    const float z = xz[(size_t)b * (2 * D_INNER) + D_INNER + d];
    const float dtxc = dt * xc;

    const size_t srow = (size_t)b * (D_INNER * STATE_W) + (size_t)d * STATE_W;
    const float4* ss = reinterpret_cast<const float4*>(rnn + srow + D_CONV);
    float4* os = reinterpret_cast<float4*>(out_states + srow + D_CONV);
    const float4* Al = reinterpret_cast<const float4*>(A_log + d * D_STATE);

    float y = 0.f;
#pragma unroll
    for (int q = 0; q < 4; q++) {
        float4 s = ss[q];
        float4 a = Al[q];
        float sn[4] = {s.x, s.y, s.z, s.w};
        float an[4] = {a.x, a.y, a.z, a.w};
        float on[4];
#pragma unroll
        for (int i = 0; i < 4; i++) {
            const int n = q * 4 + i;
            const float dA = __expf(-dt * __expf(an[i]));
            const float sv = sn[i] * dA + dtxc * sBC[n];
            on[i] = sv;
            y += sv * sBC[16 + n];
        }
        os[q] = make_float4(on[0], on[1], on[2], on[3]);
    }
    y += Dp[d] * xc;
    y *= siluf(z);
    bf16 h, l; bsplit(y, h, l);
    yh[bd] = h; yl[bd] = l;
}

// ---------------- launch ----------------
#define GETP(sym, var) float* var; cudaGetSymbolAddress((void**)&var, sym)
#define GETB(sym, var) bf16* var; cudaGetSymbolAddress((void**)&var, sym)

extern "C" void kernel_launch(void* const* d_in, const int* in_sizes, int n_in,
                              void* d_out, int out_size)
{
    const float* x          = (const float*)d_in[0];
    const float* rnn        = (const float*)d_in[1];
    const float* w_inp      = (const float*)d_in[2];
    const float* b_inp      = (const float*)d_in[3];
    const float* w_outp     = (const float*)d_in[4];
    const float* b_outp     = (const float*)d_in[5];
    const float* in_proj_w  = (const float*)d_in[6];
    const float* conv_w     = (const float*)d_in[7];
    const float* conv_b     = (const float*)d_in[8];
    const float* x_proj_w   = (const float*)d_in[9];
    const float* dt_proj_w  = (const float*)d_in[10];
    const float* dt_proj_b  = (const float*)d_in[11];
    const float* A_log      = (const float*)d_in[12];
    const float* Dp         = (const float*)d_in[13];
    const float* out_proj_w = (const float*)d_in[14];

    float* out = (float*)d_out;
    float* out_states = out + (size_t)BATCH * OUT_SIZE;

    GETP(g_xz, p_xz);   GETP(g_xc, p_xc);   GETP(g_xdb, p_xdb);  GETP(g_dt, p_dt);
    GETB(g_h_hi, hH);   GETB(g_h_lo, hL);
    GETB(g_x_hi, xH);   GETB(g_x_lo, xL);
    GETB(g_xc_hi, xcH); GETB(g_xc_lo, xcL);
    GETB(g_y_hi, yH);   GETB(g_y_lo, yL);
    GETB(g_co_hi, coH); GETB(g_co_lo, coL);
    GETB(g_xdb_hi, xdH); GETB(g_xdb_lo, xdL);
    GETB(g_w1_hi, w1H); GETB(g_w1_lo, w1L);
    GETB(g_w2_hi, w2H); GETB(g_w2_lo, w2L);
    GETB(g_w4_hi, w4H); GETB(g_w4_lo, w4L);
    GETB(g_w5_hi, w5H); GETB(g_w5_lo, w5L);
    GETB(g_w7_hi, w7H); GETB(g_w7_lo, w7L);
    GETB(g_w8_hi, w8H); GETB(g_w8_lo, w8L);

    cudaFuncSetAttribute(bgemm<0, false, false>, cudaFuncAttributeMaxDynamicSharedMemorySize, TG_SMEM);
    cudaFuncSetAttribute(bgemm<1, false, false>, cudaFuncAttributeMaxDynamicSharedMemorySize, TG_SMEM);
    cudaFuncSetAttribute(bgemm<2, false, false>, cudaFuncAttributeMaxDynamicSharedMemorySize, TG_SMEM);
    cudaFuncSetAttribute(bgemm<0, true,  false>, cudaFuncAttributeMaxDynamicSharedMemorySize, TG_SMEM);
    cudaFuncSetAttribute(bgemm<0, false, true >, cudaFuncAttributeMaxDynamicSharedMemorySize, TG_SMEM);
    cudaFuncSetAttribute(bgemm<1, false, true >, cudaFuncAttributeMaxDynamicSharedMemorySize, TG_SMEM);

    dim3 blk(256);

    // ---- weight / input splits
    split_kernel<<<(BATCH * IN_SIZE / 4 + 255) / 256, blk>>>(x, xH, xL, BATCH * IN_SIZE / 4);
    tsplit_kernel<<<dim3(D_MODEL / 32, IN_SIZE / 32), blk>>>(w_inp, w1H, w1L, IN_SIZE, D_MODEL);
    split_kernel<<<(2 * D_INNER * D_MODEL / 4 + 255) / 256, blk>>>(in_proj_w, w2H, w2L, 2 * D_INNER * D_MODEL / 4);
    split_kernel<<<(XDB_COLS * D_INNER / 4 + 255) / 256, blk>>>(x_proj_w, w4H, w4L, XDB_COLS * D_INNER / 4);
    split_kernel<<<(D_INNER * DT_RANK / 4 + 255) / 256, blk>>>(dt_proj_w, w5H, w5L, D_INNER * DT_RANK / 4);
    split_kernel<<<(D_MODEL * D_INNER / 4 + 255) / 256, blk>>>(out_proj_w, w7H, w7L, D_MODEL * D_INNER / 4);
    tsplit_kernel<<<dim3(OUT_SIZE / 32, D_MODEL / 32), blk>>>(w_outp, w8H, w8L, D_MODEL, OUT_SIZE);

    // 1) h = x @ w_inp + b_inp -> split h   (2048x1024, K=512)
    bgemm<1, false, true><<<dim3(D_MODEL / 128, BATCH / 128), blk, TG_SMEM>>>(
        xH, xL, w1H, w1L, nullptr, hH, hL, b_inp,
        BATCH, D_MODEL, IN_SIZE, IN_SIZE, IN_SIZE, D_MODEL);

    // 2) xz = h @ in_proj_w^T  (2048x4096, K=1024) -> fp32
    bgemm<0, false, false><<<dim3(2 * D_INNER / 128, BATCH / 128), blk, TG_SMEM>>>(
        hH, hL, w2H, w2L, p_xz, nullptr, nullptr, nullptr,
        BATCH, 2 * D_INNER, D_MODEL, D_MODEL, D_MODEL, 2 * D_INNER);

    // 3) conv shift + silu -> xc fp32 + split
    conv_kernel<<<(BATCH * D_INNER) / 256, blk>>>(rnn, p_xz, conv_w, conv_b, out_states, p_xc, xcH, xcL);

    // 4) xdb = xc @ x_proj_w^T  (N=96, K=2048, split-K=8)
    zero_kernel<<<(BATCH * XDB_COLS + 255) / 256, blk>>>(p_xdb, BATCH * XDB_COLS);
    bgemm<0, true, false><<<dim3(1, BATCH / 128, 8), blk, TG_SMEM>>>(
        xcH, xcL, w4H, w4L, p_xdb, nullptr, nullptr, nullptr,
        BATCH, XDB_COLS, D_INNER, D_INNER, D_INNER, XDB_COLS);
    split_kernel<<<(BATCH * XDB_COLS / 4 + 255) / 256, blk>>>(p_xdb, xdH, xdL, BATCH * XDB_COLS / 4);

    // 5) dt = softplus(xdb[:, :64] @ dt_proj_w^T + dt_proj_b)  (2048x2048, K=64)
    bgemm<2, false, false><<<dim3(D_INNER / 128, BATCH / 128), blk, TG_SMEM>>>(
        xdH, xdL, w5H, w5L, p_dt, nullptr, nullptr, dt_proj_b,
        BATCH, D_INNER, DT_RANK, XDB_COLS, DT_RANK, D_INNER);

    // 6) SSM update -> split y
    ssm_kernel<<<dim3(D_INNER / 256, BATCH), blk>>>(
        rnn, p_xz, p_xdb, p_dt, p_xc, A_log, Dp, out_states, yH, yL);

    // 7) core = y @ out_proj_w^T  (2048x1024, K=2048) -> split core
    bgemm<0, false, true><<<dim3(D_MODEL / 128, BATCH / 128), blk, TG_SMEM>>>(
        yH, yL, w7H, w7L, nullptr, coH, coL, nullptr,
        BATCH, D_MODEL, D_INNER, D_INNER, D_INNER, D_MODEL);

    // 8) out = core @ w_outp + b_outp  (2048x512, K=1024)
    bgemm<1, false, false><<<dim3(OUT_SIZE / 128, BATCH / 128), blk, TG_SMEM>>>(
        coH, coL, w8H, w8L, out, nullptr, nullptr, b_outp,
        BATCH, OUT_SIZE, D_MODEL, D_MODEL, D_MODEL, OUT_SIZE);
}

// round 7
// speedup vs baseline: 1.1549x; 1.1549x over previous
#include <cuda_runtime.h>
#include <cuda_bf16.h>
#include <math.h>
#include <stdint.h>

#define D_MODEL   1024
#define D_STATE   16
#define D_CONV    4
#define D_INNER   2048
#define DT_RANK   64
#define IN_SIZE   512
#define OUT_SIZE  512
#define BATCH     2048
#define XDB_COLS  96
#define STATE_W   20

typedef __nv_bfloat16 bf16;

// ---------------- fp32 scratch ----------------
__device__ float g_xz[BATCH * 2 * D_INNER];
__device__ float g_xc[BATCH * D_INNER];
__device__ float g_xdb[BATCH * XDB_COLS];
__device__ float g_dt[BATCH * D_INNER];
__device__ float g_bz[2 * D_INNER];
// ---------------- bf16 split scratch ----------------
__device__ bf16 g_x_hi[BATCH * IN_SIZE],   g_x_lo[BATCH * IN_SIZE];
__device__ bf16 g_xc_hi[BATCH * D_INNER],  g_xc_lo[BATCH * D_INNER];
__device__ bf16 g_y_hi[BATCH * D_INNER],   g_y_lo[BATCH * D_INNER];
__device__ bf16 g_xdb_hi[BATCH * XDB_COLS], g_xdb_lo[BATCH * XDB_COLS];
__device__ bf16 g_wi_hi[IN_SIZE * D_MODEL],     g_wi_lo[IN_SIZE * D_MODEL];      // w_inp plain
__device__ bf16 g_ip_hi[2 * D_INNER * D_MODEL], g_ip_lo[2 * D_INNER * D_MODEL];  // in_proj plain
__device__ bf16 g_wxz_hi[2 * D_INNER * IN_SIZE], g_wxz_lo[2 * D_INNER * IN_SIZE]; // W12 [4096x512]
__device__ bf16 g_w4_hi[XDB_COLS * D_INNER],    g_w4_lo[XDB_COLS * D_INNER];
__device__ bf16 g_w5_hi[D_INNER * DT_RANK],     g_w5_lo[D_INNER * DT_RANK];
__device__ bf16 g_opT_hi[D_INNER * D_MODEL],    g_opT_lo[D_INNER * D_MODEL];     // out_proj^T [2048x1024]
__device__ bf16 g_woT_hi[OUT_SIZE * D_MODEL],   g_woT_lo[OUT_SIZE * D_MODEL];    // w_outp^T [512x1024]
__device__ bf16 g_wf_hi[OUT_SIZE * D_INNER],    g_wf_lo[OUT_SIZE * D_INNER];     // Wf [512x2048]

// ---------------- helpers ----------------
__device__ __forceinline__ float softplusf(float x) {
    return (x > 0.f) ? (x + log1pf(__expf(-x))) : log1pf(__expf(x));
}
__device__ __forceinline__ float siluf(float x) {
    return x / (1.f + __expf(-x));
}
__device__ __forceinline__ void bsplit(float v, bf16& h, bf16& l) {
    h = __float2bfloat16_rn(v);
    l = __float2bfloat16_rn(v - __bfloat162float(h));
}
__device__ __forceinline__ void mmabf(float* c, const uint32_t* a, const uint32_t* b) {
    asm volatile(
        "mma.sync.aligned.m16n8k16.row.col.f32.bf16.bf16.f32 "
        "{%0,%1,%2,%3}, {%4,%5,%6,%7}, {%8,%9}, {%0,%1,%2,%3};"
        : "+f"(c[0]), "+f"(c[1]), "+f"(c[2]), "+f"(c[3])
        : "r"(a[0]), "r"(a[1]), "r"(a[2]), "r"(a[3]), "r"(b[0]), "r"(b[1]));
}
__device__ __forceinline__ void cpa16(uint32_t dst, const void* src, bool p) {
    int sz = p ? 16 : 0;
    asm volatile("cp.async.cg.shared.global [%0], [%1], 16, %2;\n"
                 :: "r"(dst), "l"(src), "r"(sz));
}

// ======================================================================
// 2xBF16-split tensor GEMM (R4-proven). C[M,N] = A[M,K] @ B[N,K]^T.
// BM=BN=128, BK=64 elem, 256 thr, warps 4(m)x2(n), warp tile 32x64.
// cp.async 2-stage. EPI: 0 none, 1 +bias, 2 +bias+softplus.
// ======================================================================
#define TG_SMEM (2 * 4 * 128 * 36 * 4)   // 147456 B

template<int EPI, bool SPLITK, bool WSPLIT>
__global__ void __launch_bounds__(256, 1)
bgemm(const bf16* __restrict__ Ahi, const bf16* __restrict__ Alo,
      const bf16* __restrict__ Bhi, const bf16* __restrict__ Blo,
      float* __restrict__ C, bf16* __restrict__ Chi, bf16* __restrict__ Clo,
      const float* __restrict__ bias,
      int M, int N, int K, int lda, int ldb, int ldc)
{
    extern __shared__ uint32_t smbuf[];
    constexpr int TSZ = 128 * 36;
    constexpr int STAGE = 4 * TSZ;

    const uint32_t* A32h = reinterpret_cast<const uint32_t*>(Ahi);
    const uint32_t* A32l = reinterpret_cast<const uint32_t*>(Alo);
    const uint32_t* B32h = reinterpret_cast<const uint32_t*>(Bhi);
    const uint32_t* B32l = reinterpret_cast<const uint32_t*>(Blo);
    const int ldap = lda >> 1, ldbp = ldb >> 1;

    const int tid  = threadIdx.x;
    const int lane = tid & 31;
    const int warp = tid >> 5;
    const int wm   = warp & 3;
    const int wn   = warp >> 2;
    const int m0   = blockIdx.y * 128;
    const int n0   = blockIdx.x * 128;
    const int Kc   = SPLITK ? (K / gridDim.z) : K;
    const int k0b  = SPLITK ? (blockIdx.z * Kc) : 0;
    const int T    = Kc / 64;

    const int lr = tid >> 3;
    const int lc = (tid & 7) * 4;

    float acc[2][8][4];
#pragma unroll
    for (int i = 0; i < 2; i++)
#pragma unroll
        for (int j = 0; j < 8; j++)
#pragma unroll
            for (int q = 0; q < 4; q++) acc[i][j][q] = 0.f;

    auto fill = [&](int t, int st) {
        uint32_t* Ah = smbuf + st * STAGE;
        uint32_t* Al = Ah + TSZ;
        uint32_t* Bh = Al + TSZ;
        uint32_t* Bl = Bh + TSZ;
        const int kp0 = (k0b + t * 64) >> 1;
#pragma unroll
        for (int it = 0; it < 4; it++) {
            const int row = lr + it * 32;
            const size_t g = (size_t)(m0 + row) * ldap + kp0 + lc;
            cpa16((uint32_t)__cvta_generic_to_shared(&Ah[row * 36 + lc]), A32h + g, true);
            cpa16((uint32_t)__cvta_generic_to_shared(&Al[row * 36 + lc]), A32l + g, true);
        }
#pragma unroll
        for (int it = 0; it < 4; it++) {
            const int row = lr + it * 32;
            const bool p = SPLITK ? ((n0 + row) < N) : true;
            const size_t g = (size_t)(n0 + row) * ldbp + kp0 + lc;
            cpa16((uint32_t)__cvta_generic_to_shared(&Bh[row * 36 + lc]), B32h + g, p);
            cpa16((uint32_t)__cvta_generic_to_shared(&Bl[row * 36 + lc]), B32l + g, p);
        }
    };

    auto compute = [&](int st) {
        uint32_t* Ah = smbuf + st * STAGE;
        uint32_t* Al = Ah + TSZ;
        uint32_t* Bh = Al + TSZ;
        uint32_t* Bl = Bh + TSZ;
#pragma unroll
        for (int ks = 0; ks < 32; ks += 8) {
            uint32_t ah[2][4], al[2][4];
#pragma unroll
            for (int mt = 0; mt < 2; mt++) {
                const int mr = wm * 32 + mt * 16 + (lane >> 2);
                const int kc = ks + (lane & 3);
                ah[mt][0] = Ah[mr * 36 + kc];
                ah[mt][1] = Ah[(mr + 8) * 36 + kc];
                ah[mt][2] = Ah[mr * 36 + kc + 4];
                ah[mt][3] = Ah[(mr + 8) * 36 + kc + 4];
                al[mt][0] = Al[mr * 36 + kc];
                al[mt][1] = Al[(mr + 8) * 36 + kc];
                al[mt][2] = Al[mr * 36 + kc + 4];
                al[mt][3] = Al[(mr + 8) * 36 + kc + 4];
            }
            uint32_t bh[8][2], bl[8][2];
#pragma unroll
            for (int nt = 0; nt < 8; nt++) {
                const int nc = wn * 64 + nt * 8 + (lane >> 2);
                const int kc = ks + (lane & 3);
                bh[nt][0] = Bh[nc * 36 + kc];
                bh[nt][1] = Bh[nc * 36 + kc + 4];
                bl[nt][0] = Bl[nc * 36 + kc];
                bl[nt][1] = Bl[nc * 36 + kc + 4];
            }
#pragma unroll
            for (int mt = 0; mt < 2; mt++)
#pragma unroll
                for (int nt = 0; nt < 8; nt++) {
                    mmabf(acc[mt][nt], ah[mt], bl[nt]);
                    mmabf(acc[mt][nt], al[mt], bh[nt]);
                    mmabf(acc[mt][nt], ah[mt], bh[nt]);
                }
        }
    };

    fill(0, 0);
    asm volatile("cp.async.commit_group;" ::: "memory");
    for (int t = 0; t < T; t++) {
        if (t + 1 < T) {
            fill(t + 1, (t + 1) & 1);
            asm volatile("cp.async.commit_group;" ::: "memory");
            asm volatile("cp.async.wait_group 1;" ::: "memory");
        } else {
            asm volatile("cp.async.wait_group 0;" ::: "memory");
        }
        __syncthreads();
        compute(t & 1);
        __syncthreads();
    }

    // ---- epilogue
#pragma unroll
    for (int mt = 0; mt < 2; mt++) {
        const int mr = m0 + wm * 32 + mt * 16 + (lane >> 2);
#pragma unroll
        for (int nt = 0; nt < 8; nt++) {
            const int nc = n0 + wn * 64 + nt * 8 + (lane & 3) * 2;
            float v0 = acc[mt][nt][0], v1 = acc[mt][nt][1];
            float v2 = acc[mt][nt][2], v3 = acc[mt][nt][3];
            if (SPLITK) {
                if (nc < N) {
                    atomicAdd(&C[(size_t)mr * ldc + nc], v0);
                    atomicAdd(&C[(size_t)mr * ldc + nc + 1], v1);
                    atomicAdd(&C[(size_t)(mr + 8) * ldc + nc], v2);
                    atomicAdd(&C[(size_t)(mr + 8) * ldc + nc + 1], v3);
                }
                continue;
            }
            if (EPI >= 1) {
                const float b0 = bias[nc], b1 = bias[nc + 1];
                v0 += b0; v1 += b1; v2 += b0; v3 += b1;
            }
            if (EPI == 2) {
                v0 = softplusf(v0); v1 = softplusf(v1);
                v2 = softplusf(v2); v3 = softplusf(v3);
            }
            if (WSPLIT) {
                bf16 h0, l0, h1, l1, h2, l2, h3, l3;
                bsplit(v0, h0, l0); bsplit(v1, h1, l1);
                bsplit(v2, h2, l2); bsplit(v3, h3, l3);
                __nv_bfloat162 ha = {h0, h1}, hb = {h2, h3};
                __nv_bfloat162 la = {l0, l1}, lb = {l2, l3};
                *reinterpret_cast<uint32_t*>(&Chi[(size_t)mr * ldc + nc])       = *(uint32_t*)&ha;
                *reinterpret_cast<uint32_t*>(&Chi[(size_t)(mr + 8) * ldc + nc]) = *(uint32_t*)&hb;
                *reinterpret_cast<uint32_t*>(&Clo[(size_t)mr * ldc + nc])       = *(uint32_t*)&la;
                *reinterpret_cast<uint32_t*>(&Clo[(size_t)(mr + 8) * ldc + nc]) = *(uint32_t*)&lb;
            } else {
                *reinterpret_cast<float2*>(&C[(size_t)mr * ldc + nc])       = make_float2(v0, v1);
                *reinterpret_cast<float2*>(&C[(size_t)(mr + 8) * ldc + nc]) = make_float2(v2, v3);
            }
        }
    }
}

// ---------------- split pass ----------------
__global__ void __launch_bounds__(256)
split_kernel(const float* __restrict__ in, bf16* __restrict__ hi,
             bf16* __restrict__ lo, int n4)
{
    int i = blockIdx.x * 256 + threadIdx.x;
    if (i < n4) {
        float4 v = reinterpret_cast<const float4*>(in)[i];
        bf16 h0, l0, h1, l1, h2, l2, h3, l3;
        bsplit(v.x, h0, l0); bsplit(v.y, h1, l1);
        bsplit(v.z, h2, l2); bsplit(v.w, h3, l3);
        __nv_bfloat162 hA = {h0, h1}, hB = {h2, h3};
        __nv_bfloat162 lA = {l0, l1}, lB = {l2, l3};
        uint2 hu = {*(uint32_t*)&hA, *(uint32_t*)&hB};
        uint2 lu = {*(uint32_t*)&lA, *(uint32_t*)&lB};
        reinterpret_cast<uint2*>(hi)[i] = hu;
        reinterpret_cast<uint2*>(lo)[i] = lu;
    }
}

// ---------------- transpose + split: KxN fp32 -> NxK bf16 hi/lo ----------------
__global__ void __launch_bounds__(256)
tsplit_kernel(const float* __restrict__ in, bf16* __restrict__ hi,
              bf16* __restrict__ lo, int K, int N)
{
    __shared__ float t[32][33];
    const int k0 = blockIdx.y * 32, n0 = blockIdx.x * 32;
    const int tx = threadIdx.x & 31, ty = threadIdx.x >> 5;
#pragma unroll
    for (int j = ty; j < 32; j += 8)
        t[j][tx] = in[(size_t)(k0 + j) * N + n0 + tx];
    __syncthreads();
#pragma unroll
    for (int j = ty; j < 32; j += 8) {
        float v = t[tx][j];
        bf16 h, l; bsplit(v, h, l);
        hi[(size_t)(n0 + j) * K + k0 + tx] = h;
        lo[(size_t)(n0 + j) * K + k0 + tx] = l;
    }
}

// ---------------- bz[n] = sum_j b_inp[j] * in_proj_w[n, j] ----------------
__global__ void __launch_bounds__(256)
bz_kernel(const float* __restrict__ b, const float* __restrict__ W,
          float* __restrict__ bz)
{
    const int w = (blockIdx.x * 256 + threadIdx.x) >> 5;   // warp -> row n
    const int lane = threadIdx.x & 31;
    if (w >= 2 * D_INNER) return;
    float s = 0.f;
    for (int j = lane; j < D_MODEL; j += 32)
        s += b[j] * W[(size_t)w * D_MODEL + j];
#pragma unroll
    for (int o = 16; o; o >>= 1) s += __shfl_xor_sync(0xFFFFFFFFu, s, o);
    if (lane == 0) bz[w] = s;
}

__global__ void zero_kernel(float* __restrict__ p, int n) {
    int i = blockIdx.x * blockDim.x + threadIdx.x;
    if (i < n) p[i] = 0.f;
}

// ---------------- conv-shift + silu ----------------
__global__ void __launch_bounds__(256)
conv_kernel(const float* __restrict__ rnn, const float* __restrict__ xz,
            const float* __restrict__ conv_w, const float* __restrict__ conv_b,
            float* __restrict__ out_states, float* __restrict__ xc,
            bf16* __restrict__ xch, bf16* __restrict__ xcl)
{
    const size_t idx = (size_t)blockIdx.x * 256 + threadIdx.x;
    const int b = (int)(idx / D_INNER);
    const int d = (int)(idx % D_INNER);
    const size_t srow = (size_t)b * (D_INNER * STATE_W) + (size_t)d * STATE_W;

    float4 cs = *reinterpret_cast<const float4*>(rnn + srow);
    float xi = xz[(size_t)b * (2 * D_INNER) + d];
    float4 w = *reinterpret_cast<const float4*>(conv_w + d * 4);

    float v = cs.y * w.x + cs.z * w.y + cs.w * w.z + xi * w.w + conv_b[d];
    float s = siluf(v);
    xc[idx] = s;
    bf16 h, l; bsplit(s, h, l);
    xch[idx] = h; xcl[idx] = l;
    *reinterpret_cast<float4*>(out_states + srow) = make_float4(cs.y, cs.z, cs.w, xi);
}

// ---------------- SSM state update + gating ----------------
__global__ void __launch_bounds__(256)
ssm_kernel(const float* __restrict__ rnn, const float* __restrict__ xz,
           const float* __restrict__ xdb, const float* __restrict__ dt_,
           const float* __restrict__ xc_, const float* __restrict__ A_log,
           const float* __restrict__ Dp,
           float* __restrict__ out_states, bf16* __restrict__ yh, bf16* __restrict__ yl)
{
    const int b = blockIdx.y;
    const int d = blockIdx.x * 256 + threadIdx.x;

    __shared__ float sBC[32];
    if (threadIdx.x < 32) sBC[threadIdx.x] = xdb[(size_t)b * XDB_COLS + DT_RANK + threadIdx.x];
    __syncthreads();

    const size_t bd = (size_t)b * D_INNER + d;
    const float dt = dt_[bd];
    const float xc = xc_[bd];
    const float z = xz[(size_t)b * (2 * D_INNER) + D_INNER + d];
    const float dtxc = dt * xc;

    const size_t srow = (size_t)b * (D_INNER * STATE_W) + (size_t)d * STATE_W;
    const float4* ss = reinterpret_cast<const float4*>(rnn + srow + D_CONV);
    float4* os = reinterpret_cast<float4*>(out_states + srow + D_CONV);
    const float4* Al = reinterpret_cast<const float4*>(A_log + d * D_STATE);

    float y = 0.f;
#pragma unroll
    for (int q = 0; q < 4; q++) {
        float4 s = ss[q];
        float4 a = Al[q];
        float sn[4] = {s.x, s.y, s.z, s.w};
        float an[4] = {a.x, a.y, a.z, a.w};
        float on[4];
#pragma unroll
        for (int i = 0; i < 4; i++) {
            const int n = q * 4 + i;
            const float dA = __expf(-dt * __expf(an[i]));
            const float sv = sn[i] * dA + dtxc * sBC[n];
            on[i] = sv;
            y += sv * sBC[16 + n];
        }
        os[q] = make_float4(on[0], on[1], on[2], on[3]);
    }
    y += Dp[d] * xc;
    y *= siluf(z);
    bf16 h, l; bsplit(y, h, l);
    yh[bd] = h; yl[bd] = l;
}

// ---------------- launch ----------------
#define GETP(sym, var) float* var; cudaGetSymbolAddress((void**)&var, sym)
#define GETB(sym, var) bf16* var; cudaGetSymbolAddress((void**)&var, sym)

extern "C" void kernel_launch(void* const* d_in, const int* in_sizes, int n_in,
                              void* d_out, int out_size)
{
    const float* x          = (const float*)d_in[0];
    const float* rnn        = (const float*)d_in[1];
    const float* w_inp      = (const float*)d_in[2];
    const float* b_inp      = (const float*)d_in[3];
    const float* w_outp     = (const float*)d_in[4];
    const float* b_outp     = (const float*)d_in[5];
    const float* in_proj_w  = (const float*)d_in[6];
    const float* conv_w     = (const float*)d_in[7];
    const float* conv_b     = (const float*)d_in[8];
    const float* x_proj_w   = (const float*)d_in[9];
    const float* dt_proj_w  = (const float*)d_in[10];
    const float* dt_proj_b  = (const float*)d_in[11];
    const float* A_log      = (const float*)d_in[12];
    const float* Dp         = (const float*)d_in[13];
    const float* out_proj_w = (const float*)d_in[14];

    float* out = (float*)d_out;
    float* out_states = out + (size_t)BATCH * OUT_SIZE;

    GETP(g_xz, p_xz);   GETP(g_xc, p_xc);   GETP(g_xdb, p_xdb);  GETP(g_dt, p_dt);
    GETP(g_bz, p_bz);
    GETB(g_x_hi, xH);   GETB(g_x_lo, xL);
    GETB(g_xc_hi, xcH); GETB(g_xc_lo, xcL);
    GETB(g_y_hi, yH);   GETB(g_y_lo, yL);
    GETB(g_xdb_hi, xdH); GETB(g_xdb_lo, xdL);
    GETB(g_wi_hi, wiH); GETB(g_wi_lo, wiL);
    GETB(g_ip_hi, ipH); GETB(g_ip_lo, ipL);
    GETB(g_wxz_hi, wxH); GETB(g_wxz_lo, wxL);
    GETB(g_w4_hi, w4H); GETB(g_w4_lo, w4L);
    GETB(g_w5_hi, w5H); GETB(g_w5_lo, w5L);
    GETB(g_opT_hi, opH); GETB(g_opT_lo, opL);
    GETB(g_woT_hi, woH); GETB(g_woT_lo, woL);
    GETB(g_wf_hi, wfH); GETB(g_wf_lo, wfL);

    cudaFuncSetAttribute(bgemm<0, false, false>, cudaFuncAttributeMaxDynamicSharedMemorySize, TG_SMEM);
    cudaFuncSetAttribute(bgemm<1, false, false>, cudaFuncAttributeMaxDynamicSharedMemorySize, TG_SMEM);
    cudaFuncSetAttribute(bgemm<2, false, false>, cudaFuncAttributeMaxDynamicSharedMemorySize, TG_SMEM);
    cudaFuncSetAttribute(bgemm<0, true,  false>, cudaFuncAttributeMaxDynamicSharedMemorySize, TG_SMEM);
    cudaFuncSetAttribute(bgemm<0, false, true >, cudaFuncAttributeMaxDynamicSharedMemorySize, TG_SMEM);

    dim3 blk(256);

    // ---- splits of inputs / weights
    split_kernel<<<(BATCH * IN_SIZE / 4 + 255) / 256, blk>>>(x, xH, xL, BATCH * IN_SIZE / 4);
    split_kernel<<<(IN_SIZE * D_MODEL / 4 + 255) / 256, blk>>>(w_inp, wiH, wiL, IN_SIZE * D_MODEL / 4);
    split_kernel<<<(2 * D_INNER * D_MODEL / 4 + 255) / 256, blk>>>(in_proj_w, ipH, ipL, 2 * D_INNER * D_MODEL / 4);
    split_kernel<<<(XDB_COLS * D_INNER / 4 + 255) / 256, blk>>>(x_proj_w, w4H, w4L, XDB_COLS * D_INNER / 4);
    split_kernel<<<(D_INNER * DT_RANK / 4 + 255) / 256, blk>>>(dt_proj_w, w5H, w5L, D_INNER * DT_RANK / 4);
    tsplit_kernel<<<dim3(D_INNER / 32, D_MODEL / 32), blk>>>(out_proj_w, opH, opL, D_MODEL, D_INNER);   // -> [2048x1024]
    tsplit_kernel<<<dim3(OUT_SIZE / 32, D_MODEL / 32), blk>>>(w_outp, woH, woL, D_MODEL, OUT_SIZE);     // -> [512x1024]

    // ---- fused weights
    // W12[n,k] = sum_j in_proj_w[n,j] * w_inp[k,j]   -> C[4096x512] bf16 split
    bgemm<0, false, true><<<dim3(IN_SIZE / 128, 2 * D_INNER / 128), blk, TG_SMEM>>>(
        ipH, ipL, wiH, wiL, nullptr, wxH, wxL, nullptr,
        2 * D_INNER, IN_SIZE, D_MODEL, D_MODEL, D_MODEL, IN_SIZE);
    // bz = b_inp @ in_proj_w^T
    bz_kernel<<<(2 * D_INNER * 32 + 255) / 256, blk>>>(b_inp, in_proj_w, p_bz);
    // Wf[n,k] = sum_j w_outp[j,n] * out_proj_w[j,k]  -> C[512x2048] bf16 split
    bgemm<0, false, true><<<dim3(D_INNER / 128, OUT_SIZE / 128), blk, TG_SMEM>>>(
        woH, woL, opH, opL, nullptr, wfH, wfL, nullptr,
        OUT_SIZE, D_INNER, D_MODEL, D_MODEL, D_MODEL, D_INNER);

    // 1+2) xz = x @ W12^T + bz   (2048x4096, K=512)
    bgemm<1, false, false><<<dim3(2 * D_INNER / 128, BATCH / 128), blk, TG_SMEM>>>(
        xH, xL, wxH, wxL, p_xz, nullptr, nullptr, p_bz,
        BATCH, 2 * D_INNER, IN_SIZE, IN_SIZE, IN_SIZE, 2 * D_INNER);

    // 3) conv shift + silu -> xc fp32 + split
    conv_kernel<<<(BATCH * D_INNER) / 256, blk>>>(rnn, p_xz, conv_w, conv_b, out_states, p_xc, xcH, xcL);

    // 4) xdb = xc @ x_proj_w^T  (N=96, K=2048, split-K=8)
    zero_kernel<<<(BATCH * XDB_COLS + 255) / 256, blk>>>(p_xdb, BATCH * XDB_COLS);
    bgemm<0, true, false><<<dim3(1, BATCH / 128, 8), blk, TG_SMEM>>>(
        xcH, xcL, w4H, w4L, p_xdb, nullptr, nullptr, nullptr,
        BATCH, XDB_COLS, D_INNER, D_INNER, D_INNER, XDB_COLS);
    split_kernel<<<(BATCH * XDB_COLS / 4 + 255) / 256, blk>>>(p_xdb, xdH, xdL, BATCH * XDB_COLS / 4);

    // 5) dt = softplus(xdb[:, :64] @ dt_proj_w^T + dt_proj_b)  (2048x2048, K=64)
    bgemm<2, false, false><<<dim3(D_INNER / 128, BATCH / 128), blk, TG_SMEM>>>(
        xdH, xdL, w5H, w5L, p_dt, nullptr, nullptr, dt_proj_b,
        BATCH, D_INNER, DT_RANK, XDB_COLS, DT_RANK, D_INNER);

    // 6) SSM update -> split y
    ssm_kernel<<<dim3(D_INNER / 256, BATCH), blk>>>(
        rnn, p_xz, p_xdb, p_dt, p_xc, A_log, Dp, out_states, yH, yL);

    // 7+8) out = y @ Wf^T + b_outp   (2048x512, K=2048)
    bgemm<1, false, false><<<dim3(OUT_SIZE / 128, BATCH / 128), blk, TG_SMEM>>>(
        yH, yL, wfH, wfL, out, nullptr, nullptr, b_outp,
        BATCH, OUT_SIZE, D_INNER, D_INNER, D_INNER, OUT_SIZE);
}